// round 10
// baseline (speedup 1.0000x reference)
#include <cuda_runtime.h>
#include <cuda.h>
#include <cuda_bf16.h>
#include <math.h>
#include <float.h>
#include <stdint.h>

#define N_SEQ 1536
#define NB    2
#define HEADS 8
#define DK    64
#define DV    192
#define DIM   1536
#define FS    192
#define HDK   (HEADS*DK)
#define HDV   (HEADS*DV)
#define MROWS (NB*N_SEQ)   // 3072
#define NQKV  2560

__device__ __align__(1024) __nv_bfloat16 g_xs   [2*MROWS*DIM];
__device__ __align__(1024) __nv_bfloat16 g_ws   [2*NQKV*DIM];
__device__ __align__(1024) __nv_bfloat16 g_wouts[2*DIM*HDV];
__device__ __align__(1024) __nv_bfloat16 g_wrels[2*HDK*FS];
__device__ __align__(1024) __nv_bfloat16 g_poss [2*MROWS*FS];
__device__ __align__(1024) __nv_bfloat16 g_Os   [2*MROWS*HDV];
__device__ __align__(1024) __nv_bfloat16 g_Ks   [2*MROWS*HDK];
__device__ __align__(1024) __nv_bfloat16 g_Vts  [2*HDV*MROWS];
__device__ __align__(1024) __nv_bfloat16 g_relks[2*MROWS*HDK];
__device__ __align__(1024) float g_Q   [MROWS*HDK];

#define XS_PLANE    ((size_t)MROWS*DIM)
#define WS_PLANE    ((size_t)NQKV*DIM)
#define WOUTS_PLANE ((size_t)DIM*HDV)
#define WRELS_PLANE ((size_t)HDK*FS)
#define POSS_PLANE  ((size_t)MROWS*FS)
#define OS_PLANE    ((size_t)MROWS*HDV)
#define KS_PLANE    ((size_t)MROWS*HDK)
#define VTS_PLANE   ((size_t)HDV*MROWS)
#define RELKS_PLANE ((size_t)MROWS*HDK)

__device__ __forceinline__ void bsplit(float v, __nv_bfloat16& h, __nv_bfloat16& l) {
    h = __float2bfloat16(v);
    l = __float2bfloat16(__fsub_rn(v, __bfloat162float(h)));
}
__device__ __forceinline__ uint32_t smem_u32(const void* p) {
    uint32_t a;
    asm("{ .reg .u64 t; cvta.to.shared.u64 t, %1; cvt.u32.u64 %0, t; }" : "=r"(a) : "l"(p));
    return a;
}
__device__ __forceinline__ void mbar_init(uint32_t a, uint32_t c) {
    asm volatile("mbarrier.init.shared.b64 [%0], %1;" :: "r"(a), "r"(c) : "memory");
}
__device__ __forceinline__ void mbar_expect_tx(uint32_t a, uint32_t b) {
    asm volatile("mbarrier.arrive.expect_tx.shared.b64 _, [%0], %1;" :: "r"(a), "r"(b) : "memory");
}
__device__ __forceinline__ void mbar_wait(uint32_t a, uint32_t ph) {
    asm volatile(
        "{\n\t.reg .pred P;\n\t"
        "W%=:\n\t"
        "mbarrier.try_wait.parity.acquire.cta.shared::cta.b64 P, [%0], %1, 0x989680;\n\t"
        "@P bra.uni D%=;\n\t"
        "bra.uni W%=;\n\t"
        "D%=:\n\t}"
        :: "r"(a), "r"(ph) : "memory");
}
__device__ __forceinline__ void tma3d(uint32_t dst, const CUtensorMap* tm, int x, int y, int z, uint32_t bar) {
    asm volatile(
        "cp.async.bulk.tensor.3d.shared::cta.global.tile.mbarrier::complete_tx::bytes "
        "[%0], [%1, {%2, %3, %4}], [%5];"
        :: "r"(dst), "l"(tm), "r"(x), "r"(y), "r"(z), "r"(bar) : "memory");
}
__device__ __forceinline__ void ldm4(uint32_t* r, uint32_t addr) {
    asm volatile("ldmatrix.sync.aligned.m8n8.x4.shared.b16 {%0,%1,%2,%3}, [%4];"
                 : "=r"(r[0]), "=r"(r[1]), "=r"(r[2]), "=r"(r[3]) : "r"(addr));
}
__device__ __forceinline__ void mma_bf16(float* c, const uint32_t* a, uint32_t b0, uint32_t b1) {
    asm volatile("mma.sync.aligned.m16n8k16.row.col.f32.bf16.bf16.f32 "
                 "{%0,%1,%2,%3}, {%4,%5,%6,%7}, {%8,%9}, {%0,%1,%2,%3};"
                 : "+f"(c[0]), "+f"(c[1]), "+f"(c[2]), "+f"(c[3])
                 : "r"(a[0]), "r"(a[1]), "r"(a[2]), "r"(a[3]), "r"(b0), "r"(b1));
}

// ---------------- split helpers ----------------
__device__ __forceinline__ void split_quad(const float* __restrict__ src,
                                           __nv_bfloat16* __restrict__ dh,
                                           __nv_bfloat16* __restrict__ dl, int i) {
    float4 v = ((const float4*)src)[i];
    __nv_bfloat16 h0,l0,h1,l1,h2,l2,h3,l3;
    bsplit(v.x,h0,l0); bsplit(v.y,h1,l1); bsplit(v.z,h2,l2); bsplit(v.w,h3,l3);
    ((__nv_bfloat162*)dh)[2*i]   = __halves2bfloat162(h0,h1);
    ((__nv_bfloat162*)dh)[2*i+1] = __halves2bfloat162(h2,h3);
    ((__nv_bfloat162*)dl)[2*i]   = __halves2bfloat162(l0,l1);
    ((__nv_bfloat162*)dl)[2*i+1] = __halves2bfloat162(l2,l3);
}

__global__ void split_x(const float* __restrict__ x) {
    int i = blockIdx.x * 256 + threadIdx.x;
    if (i < MROWS*DIM/4) split_quad(x, g_xs, g_xs + XS_PLANE, i);
}

// ---------------- fp32-exact transcendentals + XLA lgamma ----------------
__device__ __forceinline__ float logf_cr(float x)   { return (float)log((double)x); }
__device__ __forceinline__ float log1pf_cr(float x) { return (float)log1p((double)x); }
__device__ __forceinline__ float expf_cr(float x)   { return (float)exp((double)x); }

__device__ float lgamma_xla_f32(float input) {
    const float kCoef[8] = {
        676.520368121885098567009190444019f, -1259.13921672240287047156078755283f,
        771.3234287776530788486528258894f,   -176.61502916214059906584551354f,
        12.507343278686904814458936853f,     -0.13857109526572011689554707f,
        9.984369578019570859563e-6f,         1.50563273514931155834e-7f};
    float z = __fsub_rn(input, 1.f);
    float x = 0.99999999999980993227684700473478f;
    #pragma unroll
    for (int i = 0; i < 8; i++)
        x = __fadd_rn(x, __fdiv_rn(kCoef[i], __fadd_rn(__fadd_rn(z, (float)i), 1.f)));
    float t     = __fadd_rn(7.5f, z);
    float log_t = __fadd_rn(2.01490302054226772453f, log1pf_cr(__fdiv_rn(z, 7.5f)));
    float term  = __fmul_rn(__fsub_rn(__fadd_rn(z, 0.5f), __fdiv_rn(t, log_t)), log_t);
    return __fadd_rn(__fadd_rn(0.91893853320467274178f, term), logf_cr(x));
}

// ---------------- fused prep: pos-embed blocks + weight-split blocks ----------------
#define WQ_Q   (HDK*DIM/4)
#define WV_Q   (HDV*DIM/4)
#define WREL_Q (HDK*FS/4)
#define WOUT_Q (DIM*HDV/4)
#define WTOT_Q (WQ_Q*2 + WV_Q + WREL_Q + WOUT_Q)
#define PREP_BLOCKS (MROWS + (WTOT_Q + 255)/256)

__global__ void prep_kernel(const float* __restrict__ Wq, const float* __restrict__ Wk,
                            const float* __restrict__ Wv, const float* __restrict__ Wrel,
                            const float* __restrict__ Wout) {
    if (blockIdx.x >= MROWS) {
        int i = (blockIdx.x - MROWS) * 256 + threadIdx.x;
        if (i >= WTOT_Q) return;
        if (i < WQ_Q)   { split_quad(Wq,   g_ws,            g_ws + WS_PLANE,            i); return; }
        i -= WQ_Q;
        if (i < WQ_Q)   { split_quad(Wk,   g_ws + 512*DIM,  g_ws + WS_PLANE + 512*DIM,  i); return; }
        i -= WQ_Q;
        if (i < WV_Q)   { split_quad(Wv,   g_ws + 1024*DIM, g_ws + WS_PLANE + 1024*DIM, i); return; }
        i -= WV_Q;
        if (i < WREL_Q) { split_quad(Wrel, g_wrels,         g_wrels + WRELS_PLANE,      i); return; }
        i -= WREL_Q;
        split_quad(Wout, g_wouts, g_wouts + WOUTS_PLANE, i);
        return;
    }
    int p = blockIdx.x, t = threadIdx.x;
    size_t base = (size_t)p * FS;
    __shared__ float gprob[32];
    if (p == MROWS - 1) {
        if (t < 96) {
            g_poss[base + t] = __float2bfloat16(0.f);
            g_poss[base + t + POSS_PLANE] = __float2bfloat16(0.f);
            g_poss[base + 96 + t] = __float2bfloat16(0.f);
            g_poss[base + 96 + t + POSS_PLANE] = __float2bfloat16(0.f);
        }
        return;
    }
    const double LN2 = 0.6931471805599453;
    double adist = fabs((double)(p - (N_SEQ - 1)));
    float adist_f = (float)adist;
    float sgn = (p > N_SEQ-1) ? 1.f : ((p < N_SEQ-1) ? -1.f : 0.f);
    float val = 0.f;
    if (t < 32) {
        double max_range = log((double)N_SEQ) / LN2;
        double hl = exp2(3.0 + (double)t * (max_range - 3.0) / 31.0);
        val = (float)exp(-LN2 / hl * adist);
    } else if (t < 64) {
        double width = exp2((double)(t - 31)) - 1.0;
        val = (width > adist) ? 1.f : 0.f;
    } else if (t < 96) {
        int c = t - 64;
        float mean = 48.f * (float)(c + 1);
        float cc   = __fdiv_rn(mean, 24.f);
        float conc = __fmul_rn(cc, cc);
        float rate = __fdiv_rn(mean, 576.f);
        float log_unnorm = __fsub_rn(__fmul_rn(__fsub_rn(conc, 1.f), logf_cr(adist_f)),
                                     __fmul_rn(rate, adist_f));
        float log_norm   = __fsub_rn(lgamma_xla_f32(conc), __fmul_rn(conc, logf_cr(rate)));
        gprob[c] = __fadd_rn(expf_cr(__fsub_rn(log_unnorm, log_norm)), 1e-8f);
    }
    __syncthreads();
    if (t >= 64 && t < 96) {
        float mx = gprob[0];
        #pragma unroll
        for (int i = 1; i < 32; i++) mx = fmaxf(mx, gprob[i]);
        val = __fdiv_rn(gprob[t - 64], mx);
    }
    if (t < 96) {
        __nv_bfloat16 h, l;
        bsplit(val, h, l);
        g_poss[base + t] = h; g_poss[base + t + POSS_PLANE] = l;
        bsplit(sgn * val, h, l);
        g_poss[base + 96 + t] = h; g_poss[base + 96 + t + POSS_PLANE] = l;
    }
}

// ---------------- bf16x2 GEMM via mma.sync + TMA: C[M,N] = A·B^T ----------------
#define G_ABYTES 32768
#define G_BBYTES 65536
#define G_BUF    (G_ABYTES + G_BBYTES)
#define GSO_BF   0
#define GSO_TL   1024
#define GSMEM    (GSO_TL + 2*G_BUF)
#define VT_STRIDE 136

template<int MODE>
__global__ __launch_bounds__(256) void gemm_mma(
    const __grid_constant__ CUtensorMap tmA,
    const __grid_constant__ CUtensorMap tmB,
    const __grid_constant__ CUtensorMap tmA2,
    const __grid_constant__ CUtensorMap tmB2,
    float* __restrict__ C0, const float* __restrict__ bias, int nchunks, int ldc)
{
    extern __shared__ __align__(1024) char smem[];
    const uint32_t sb = smem_u32(smem);
    const int tid = threadIdx.x, wid = tid >> 5, lane = tid & 31;
    const int m0 = blockIdx.y * 128;
    const bool isRel = (MODE == 1) && (blockIdx.x >= 10);
    const CUtensorMap* pA = isRel ? &tmA2 : &tmA;
    const CUtensorMap* pB = isRel ? &tmB2 : &tmB;
    const int n0 = isRel ? (blockIdx.x - 10) * 256 : blockIdx.x * 256;
    const int nch = isRel ? 3 : nchunks;
    const int wr = wid >> 2, wc = wid & 3;

    if (tid == 0) {
        mbar_init(sb + GSO_BF, 1);
        mbar_init(sb + GSO_BF + 8, 1);
        asm volatile("fence.proxy.async.shared::cta;" ::: "memory");
    }
    __syncthreads();
    if (tid == 0) {
        #pragma unroll
        for (int c = 0; c < 2; c++) {
            uint32_t buf = sb + GSO_TL + c * G_BUF, bar = sb + GSO_BF + 8 * c;
            mbar_expect_tx(bar, G_BUF);
            tma3d(buf,            pA, c * 64, m0, 0, bar);
            tma3d(buf + G_ABYTES, pB, c * 64, n0, 0, bar);
        }
    }

    const uint32_t aBase = (uint32_t)(wr*64 + (lane & 15)) * 128;
    const uint32_t axk   = (uint32_t)((lane & 7) << 4);
    const uint32_t akh   = (uint32_t)((lane >> 4) * 16);
    const int bRowLow    = (lane & 7) + ((lane >> 4) & 1) * 8;
    const uint32_t bkh   = (uint32_t)(((lane >> 3) & 1) * 16);

    float acc[4][8][4];
    #pragma unroll
    for (int f = 0; f < 4; f++)
        #pragma unroll
        for (int g = 0; g < 8; g++)
            #pragma unroll
            for (int q = 0; q < 4; q++) acc[f][g][q] = 0.f;

    for (int c = 0; c < nch; c++) {
        mbar_wait(sb + GSO_BF + 8 * (c & 1), (uint32_t)((c >> 1) & 1));
        const uint32_t bufb = sb + GSO_TL + (c & 1) * G_BUF;
        #pragma unroll
        for (int ks = 0; ks < 4; ks++) {
            const uint32_t kb = (uint32_t)(ks * 32);
            const uint32_t aoff = (kb + akh) ^ axk;
            uint32_t Ah[4][4], Al[4][4];
            #pragma unroll
            for (int f = 0; f < 4; f++) ldm4(Ah[f], bufb + aBase + f * 2048 + aoff);
            #pragma unroll
            for (int f = 0; f < 4; f++) ldm4(Al[f], bufb + 16384 + aBase + f * 2048 + aoff);
            #pragma unroll
            for (int gg = 0; gg < 4; gg++) {
                uint32_t brow = (uint32_t)(wc*64 + gg*16 + bRowLow);
                uint32_t bo = brow * 128 + ((kb + bkh) ^ axk);
                uint32_t Bh[4], Bl[4];
                ldm4(Bh, bufb + 32768 + bo);
                ldm4(Bl, bufb + 65536 + bo);
                #pragma unroll
                for (int f = 0; f < 4; f++) {
                    mma_bf16(acc[f][gg*2+0], Ah[f], Bh[0], Bh[1]);
                    mma_bf16(acc[f][gg*2+1], Ah[f], Bh[2], Bh[3]);
                }
                #pragma unroll
                for (int f = 0; f < 4; f++) {
                    mma_bf16(acc[f][gg*2+0], Ah[f], Bl[0], Bl[1]);
                    mma_bf16(acc[f][gg*2+1], Ah[f], Bl[2], Bl[3]);
                }
                #pragma unroll
                for (int f = 0; f < 4; f++) {
                    mma_bf16(acc[f][gg*2+0], Al[f], Bh[0], Bh[1]);
                    mma_bf16(acc[f][gg*2+1], Al[f], Bh[2], Bh[3]);
                }
            }
        }
        __syncthreads();
        if (tid == 0 && c + 2 < nch) {
            uint32_t buf = sb + GSO_TL + (c & 1) * G_BUF, bar = sb + GSO_BF + 8 * (c & 1);
            mbar_expect_tx(bar, G_BUF);
            tma3d(buf,            pA, (c + 2) * 64, m0, 0, bar);
            tma3d(buf + G_ABYTES, pB, (c + 2) * 64, n0, 0, bar);
        }
    }

    // ---------------- epilogue ----------------
    if (MODE == 1 && !isRel && n0 >= 1024) {
        __nv_bfloat16* sTh = (__nv_bfloat16*)(smem + GSO_TL);
        __nv_bfloat16* sTl = sTh + 256 * VT_STRIDE;
        #pragma unroll
        for (int f = 0; f < 4; f++) {
            int mloc = wr*64 + f*16 + (lane >> 2);
            #pragma unroll
            for (int gg = 0; gg < 4; gg++)
                #pragma unroll
                for (int s = 0; s < 2; s++) {
                    int cn = wc*64 + gg*16 + s*8 + (lane & 3)*2;
                    const float* a = acc[f][gg*2+s];
                    __nv_bfloat16 h0,l0,h1,l1,h2,l2,h3,l3;
                    bsplit(a[0],h0,l0); bsplit(a[1],h1,l1);
                    bsplit(a[2],h2,l2); bsplit(a[3],h3,l3);
                    sTh[cn*VT_STRIDE + mloc]         = h0;
                    sTh[(cn+1)*VT_STRIDE + mloc]     = h1;
                    sTh[cn*VT_STRIDE + mloc + 8]     = h2;
                    sTh[(cn+1)*VT_STRIDE + mloc + 8] = h3;
                    sTl[cn*VT_STRIDE + mloc]         = l0;
                    sTl[(cn+1)*VT_STRIDE + mloc]     = l1;
                    sTl[cn*VT_STRIDE + mloc + 8]     = l2;
                    sTl[(cn+1)*VT_STRIDE + mloc + 8] = l3;
                }
        }
        __syncthreads();
        int r = tid;
        size_t gbase = (size_t)(n0 - 1024 + r) * 3072 + m0;
        const uint4* sph = (const uint4*)(sTh + r * VT_STRIDE);
        const uint4* spl = (const uint4*)(sTl + r * VT_STRIDE);
        uint4* dph = (uint4*)(g_Vts + gbase);
        uint4* dpl = (uint4*)(g_Vts + VTS_PLANE + gbase);
        #pragma unroll
        for (int q = 0; q < 16; q++) dph[q] = sph[q];
        #pragma unroll
        for (int q = 0; q < 16; q++) dpl[q] = spl[q];
        return;
    }
    #pragma unroll
    for (int f = 0; f < 4; f++) {
        int m = m0 + wr*64 + f*16 + (lane >> 2);
        #pragma unroll
        for (int gg = 0; gg < 4; gg++)
            #pragma unroll
            for (int s = 0; s < 2; s++) {
                int cn = wc*64 + gg*16 + s*8 + (lane & 3)*2;
                float v0 = acc[f][gg*2+s][0], v1 = acc[f][gg*2+s][1];
                float v2 = acc[f][gg*2+s][2], v3 = acc[f][gg*2+s][3];
                if (MODE == 2) {
                    float2 bv = *(const float2*)(bias + n0 + cn);
                    v0 += bv.x; v1 += bv.y; v2 += bv.x; v3 += bv.y;
                    *(float2*)(C0 + (size_t)m * ldc + n0 + cn)       = make_float2(v0, v1);
                    *(float2*)(C0 + (size_t)(m + 8) * ldc + n0 + cn) = make_float2(v2, v3);
                } else if (isRel) {
                    __nv_bfloat16 h0,l0,h1,l1;
                    bsplit(v0,h0,l0); bsplit(v1,h1,l1);
                    *(__nv_bfloat162*)(g_relks + (size_t)m*512 + n0 + cn) = __halves2bfloat162(h0,h1);
                    *(__nv_bfloat162*)(g_relks + RELKS_PLANE + (size_t)m*512 + n0 + cn) = __halves2bfloat162(l0,l1);
                    bsplit(v2,h0,l0); bsplit(v3,h1,l1);
                    *(__nv_bfloat162*)(g_relks + (size_t)(m+8)*512 + n0 + cn) = __halves2bfloat162(h0,h1);
                    *(__nv_bfloat162*)(g_relks + RELKS_PLANE + (size_t)(m+8)*512 + n0 + cn) = __halves2bfloat162(l0,l1);
                } else if (n0 < 512) {
                    *(float2*)(g_Q + (size_t)m * 512 + n0 + cn)       = make_float2(v0, v1);
                    *(float2*)(g_Q + (size_t)(m + 8) * 512 + n0 + cn) = make_float2(v2, v3);
                } else {
                    int kc = n0 - 512 + cn;
                    __nv_bfloat16 h0,l0,h1,l1;
                    bsplit(v0,h0,l0); bsplit(v1,h1,l1);
                    *(__nv_bfloat162*)(g_Ks + (size_t)m*512 + kc) = __halves2bfloat162(h0,h1);
                    *(__nv_bfloat162*)(g_Ks + KS_PLANE + (size_t)m*512 + kc) = __halves2bfloat162(l0,l1);
                    bsplit(v2,h0,l0); bsplit(v3,h1,l1);
                    *(__nv_bfloat162*)(g_Ks + (size_t)(m+8)*512 + kc) = __halves2bfloat162(h0,h1);
                    *(__nv_bfloat162*)(g_Ks + KS_PLANE + (size_t)(m+8)*512 + kc) = __halves2bfloat162(l0,l1);
                }
            }
    }
}

// ---------------- tensor-core flash attention with relative shift ----------------
// 8 warps = (wq = wid&3: N-slice) x (rh = wid>>2: 32-row half).
// R: warp 32 rows x 32 p; S: 32 rows x 16 j; PV: 32 rows x 48 d.
#define A_SQ    0          // qch 0, qcl 8192, qrh 16384, qrl 24576
#define A_SK    32768
#define A_SREL  49152
#define A_SV    81920
#define A_SP    131072
#define A_SR    147456     // fp32 64 x 132
#define A_SPM   181248     // pmax [4][64]
#define A_SPS   182272     // psum [4][64]
#define A_SBAR  183296
#define A_SMEM  183312

__global__ __launch_bounds__(256) void attn_mma(
    const __grid_constant__ CUtensorMap tmK,
    const __grid_constant__ CUtensorMap tmRel,
    const __grid_constant__ CUtensorMap tmVt,
    const float* __restrict__ rcb, const float* __restrict__ rpb)
{
    extern __shared__ __align__(1024) char smem[];
    const uint32_t sb = smem_u32(smem);
    const int tid = threadIdx.x, wid = tid >> 5, lane = tid & 31;
    const int wq = wid & 3, rh = wid >> 2;
    const int bh = blockIdx.y, bb = bh >> 3, h = bh & 7;
    const int i0 = blockIdx.x * 64;

    float* Rsm  = (float*)(smem + A_SR);
    float* pmax = (float*)(smem + A_SPM);
    float* psum = (float*)(smem + A_SPS);
    const uint32_t bKR = sb + A_SBAR, bV = sb + A_SBAR + 8;

    if (tid == 0) {
        mbar_init(bKR, 1); mbar_init(bV, 1);
        asm volatile("fence.proxy.async.shared::cta;" ::: "memory");
    }
    __syncthreads();
    if (tid == 0) {
        mbar_expect_tx(bKR, 49152);
        tma3d(sb + A_SK,   &tmK,   h*64, bb*1536, 0, bKR);
        tma3d(sb + A_SREL, &tmRel, h*64, 1472 - i0, 0, bKR);
        mbar_expect_tx(bV, 49152);
        tma3d(sb + A_SV,   &tmVt,  bb*1536, h*192, 0, bV);
    }
    // build Q tiles
    {
        int row = tid >> 2;
        int c0 = (tid & 3) * 16;
        const float* qrow = g_Q + (size_t)(bb*1536 + i0 + row)*512 + h*64 + c0;
        const float* cb = rcb + h*64 + c0;
        const float* pb = rpb + h*64 + c0;
        uint32_t rx = (uint32_t)((row & 7) << 4);
        #pragma unroll
        for (int c = 0; c < 16; c += 2) {
            float q0 = qrow[c]*0.125f, q1 = qrow[c+1]*0.125f;
            float a0 = q0 + cb[c], a1 = q1 + cb[c+1];
            float b0 = q0 + pb[c], b1 = q1 + pb[c+1];
            uint32_t off = (uint32_t)row*128 + (((uint32_t)(c0 + c)*2) ^ rx);
            __nv_bfloat16 h0,l0,h1,l1;
            bsplit(a0,h0,l0); bsplit(a1,h1,l1);
            *(__nv_bfloat162*)(smem + A_SQ + off)        = __halves2bfloat162(h0,h1);
            *(__nv_bfloat162*)(smem + A_SQ + 8192 + off) = __halves2bfloat162(l0,l1);
            bsplit(b0,h0,l0); bsplit(b1,h1,l1);
            *(__nv_bfloat162*)(smem + A_SQ + 16384 + off) = __halves2bfloat162(h0,h1);
            *(__nv_bfloat162*)(smem + A_SQ + 24576 + off) = __halves2bfloat162(l0,l1);
        }
    }
    __syncthreads();

    const uint32_t aOff0 = (uint32_t)(rh*32 + (lane & 15)) * 128;   // A frag rf=0; rf=1 -> +2048
    const uint32_t axk   = (uint32_t)((lane & 7) << 4);
    const uint32_t akh   = (uint32_t)((lane >> 4) * 16);
    const int bRowLow    = (lane & 7) + ((lane >> 4) & 1) * 8;
    const uint32_t bkh   = (uint32_t)(((lane >> 3) & 1) * 16);
    const int r0 = rh*32 + (lane >> 2);   // rows: r0+rf*16 (+8)

    float Oa[2][6][4];
    #pragma unroll
    for (int rf = 0; rf < 2; rf++)
        #pragma unroll
        for (int g = 0; g < 6; g++)
            #pragma unroll
            for (int q = 0; q < 4; q++) Oa[rf][g][q] = 0.f;
    float mreg[2][2] = {{-1e30f,-1e30f},{-1e30f,-1e30f}};
    float lreg[2][2] = {{0.f,0.f},{0.f,0.f}};

    #pragma unroll 1
    for (int jt = 0; jt < 24; jt++) {
        uint32_t ph = (uint32_t)(jt & 1);
        mbar_wait(bKR, ph);

        // --- R = Qr . relk^T : warp covers 32 rows x 32 p (p-slice wq) ---
        float Rc[2][4][4];
        #pragma unroll
        for (int rf = 0; rf < 2; rf++)
            #pragma unroll
            for (int g = 0; g < 4; g++)
                #pragma unroll
                for (int q = 0; q < 4; q++) Rc[rf][g][q] = 0.f;
        #pragma unroll
        for (int ks = 0; ks < 4; ks++) {
            uint32_t ao = ((uint32_t)(ks*32) + akh) ^ axk;
            uint32_t qh[2][4], ql[2][4];
            #pragma unroll
            for (int rf = 0; rf < 2; rf++) {
                ldm4(qh[rf], sb + A_SQ + 16384 + aOff0 + rf*2048 + ao);
                ldm4(ql[rf], sb + A_SQ + 24576 + aOff0 + rf*2048 + ao);
            }
            uint32_t bhh[2][4], bll[2][4];
            #pragma unroll
            for (int bf = 0; bf < 2; bf++) {
                uint32_t rowb = (uint32_t)(wq*32 + bf*16 + bRowLow);
                uint32_t bo = rowb*128 + (((uint32_t)(ks*32) + bkh) ^ axk);
                ldm4(bhh[bf], sb + A_SREL + bo);
                ldm4(bll[bf], sb + A_SREL + 16384 + bo);
            }
            #pragma unroll
            for (int rf = 0; rf < 2; rf++)
                #pragma unroll
                for (int bf = 0; bf < 2; bf++)
                    #pragma unroll
                    for (int s = 0; s < 2; s++)
                        mma_bf16(Rc[rf][bf*2+s], qh[rf], bhh[bf][s*2], bhh[bf][s*2+1]);
            #pragma unroll
            for (int rf = 0; rf < 2; rf++)
                #pragma unroll
                for (int bf = 0; bf < 2; bf++)
                    #pragma unroll
                    for (int s = 0; s < 2; s++)
                        mma_bf16(Rc[rf][bf*2+s], qh[rf], bll[bf][s*2], bll[bf][s*2+1]);
            #pragma unroll
            for (int rf = 0; rf < 2; rf++)
                #pragma unroll
                for (int bf = 0; bf < 2; bf++)
                    #pragma unroll
                    for (int s = 0; s < 2; s++)
                        mma_bf16(Rc[rf][bf*2+s], ql[rf], bhh[bf][s*2], bhh[bf][s*2+1]);
        }
        #pragma unroll
        for (int rf = 0; rf < 2; rf++) {
            int r = r0 + rf*16;
            #pragma unroll
            for (int g = 0; g < 4; g++) {
                int p = wq*32 + g*8 + (lane & 3)*2;
                *(float2*)(Rsm + r*132 + p)     = make_float2(Rc[rf][g][0], Rc[rf][g][1]);
                *(float2*)(Rsm + (r+8)*132 + p) = make_float2(Rc[rf][g][2], Rc[rf][g][3]);
            }
        }

        // --- content S = Qc . K^T : warp covers 32 rows x 16 j (j-slice wq) ---
        float Sc[2][2][4];
        #pragma unroll
        for (int rf = 0; rf < 2; rf++)
            #pragma unroll
            for (int s = 0; s < 2; s++)
                #pragma unroll
                for (int q = 0; q < 4; q++) Sc[rf][s][q] = 0.f;
        #pragma unroll
        for (int ks = 0; ks < 4; ks++) {
            uint32_t ao = ((uint32_t)(ks*32) + akh) ^ axk;
            uint32_t qh[2][4], ql[2][4];
            #pragma unroll
            for (int rf = 0; rf < 2; rf++) {
                ldm4(qh[rf], sb + A_SQ + aOff0 + rf*2048 + ao);
                ldm4(ql[rf], sb + A_SQ + 8192 + aOff0 + rf*2048 + ao);
            }
            uint32_t kh[4], kl[4];
            {
                uint32_t rowb = (uint32_t)(wq*16 + bRowLow);
                uint32_t bo = rowb*128 + (((uint32_t)(ks*32) + bkh) ^ axk);
                ldm4(kh, sb + A_SK + bo);
                ldm4(kl, sb + A_SK + 8192 + bo);
            }
            #pragma unroll
            for (int rf = 0; rf < 2; rf++)
                #pragma unroll
                for (int s = 0; s < 2; s++)
                    mma_bf16(Sc[rf][s], qh[rf], kh[s*2], kh[s*2+1]);
            #pragma unroll
            for (int rf = 0; rf < 2; rf++)
                #pragma unroll
                for (int s = 0; s < 2; s++)
                    mma_bf16(Sc[rf][s], qh[rf], kl[s*2], kl[s*2+1]);
            #pragma unroll
            for (int rf = 0; rf < 2; rf++)
                #pragma unroll
                for (int s = 0; s < 2; s++)
                    mma_bf16(Sc[rf][s], ql[rf], kh[s*2], kh[s*2+1]);
        }
        __syncthreads();   // R complete everywhere; K/rel smem consumed
        if (tid == 0 && jt + 1 < 24) {
            mbar_expect_tx(bKR, 49152);
            tma3d(sb + A_SK,   &tmK,   h*64, bb*1536 + (jt+1)*64, 0, bKR);
            tma3d(sb + A_SREL, &tmRel, h*64, (jt+1)*64 - i0 + 1472, 0, bKR);
        }

        // --- gather rel logits: S[i,j] += R[i, j-i+63] ---
        #pragma unroll
        for (int rf = 0; rf < 2; rf++) {
            int r = r0 + rf*16;
            #pragma unroll
            for (int s = 0; s < 2; s++) {
                int j = wq*16 + s*8 + (lane & 3)*2;
                Sc[rf][s][0] += Rsm[r*132 + (j - r + 63)];
                Sc[rf][s][1] += Rsm[r*132 + (j - r + 64)];
                Sc[rf][s][2] += Rsm[(r+8)*132 + (j - (r+8) + 63)];
                Sc[rf][s][3] += Rsm[(r+8)*132 + (j - (r+8) + 64)];
            }
        }

        // --- online softmax (cross-slice via smem partials [4][64]) ---
        float mx[2][2];
        #pragma unroll
        for (int rf = 0; rf < 2; rf++) {
            mx[rf][0] = fmaxf(fmaxf(Sc[rf][0][0], Sc[rf][0][1]), fmaxf(Sc[rf][1][0], Sc[rf][1][1]));
            mx[rf][1] = fmaxf(fmaxf(Sc[rf][0][2], Sc[rf][0][3]), fmaxf(Sc[rf][1][2], Sc[rf][1][3]));
        }
        #pragma unroll
        for (int rf = 0; rf < 2; rf++)
            #pragma unroll
            for (int hh = 0; hh < 2; hh++) {
                mx[rf][hh] = fmaxf(mx[rf][hh], __shfl_xor_sync(0xffffffffu, mx[rf][hh], 1));
                mx[rf][hh] = fmaxf(mx[rf][hh], __shfl_xor_sync(0xffffffffu, mx[rf][hh], 2));
            }
        if ((lane & 3) == 0) {
            #pragma unroll
            for (int rf = 0; rf < 2; rf++) {
                pmax[wq*64 + r0 + rf*16]     = mx[rf][0];
                pmax[wq*64 + r0 + rf*16 + 8] = mx[rf][1];
            }
        }
        __syncthreads();
        float mn[2][2], al[2][2];
        #pragma unroll
        for (int rf = 0; rf < 2; rf++)
            #pragma unroll
            for (int hh = 0; hh < 2; hh++) {
                int row = r0 + rf*16 + hh*8;
                float mval = fmaxf(fmaxf(pmax[row], pmax[64 + row]),
                                   fmaxf(pmax[128 + row], pmax[192 + row]));
                mn[rf][hh] = fmaxf(mreg[rf][hh], mval);
                al[rf][hh] = __expf(mreg[rf][hh] - mn[rf][hh]);
                mreg[rf][hh] = mn[rf][hh];
            }
        float sm[2][2] = {{0.f,0.f},{0.f,0.f}};
        #pragma unroll
        for (int rf = 0; rf < 2; rf++)
            #pragma unroll
            for (int s = 0; s < 2; s++) {
                Sc[rf][s][0] = __expf(Sc[rf][s][0] - mn[rf][0]); sm[rf][0] += Sc[rf][s][0];
                Sc[rf][s][1] = __expf(Sc[rf][s][1] - mn[rf][0]); sm[rf][0] += Sc[rf][s][1];
                Sc[rf][s][2] = __expf(Sc[rf][s][2] - mn[rf][1]); sm[rf][1] += Sc[rf][s][2];
                Sc[rf][s][3] = __expf(Sc[rf][s][3] - mn[rf][1]); sm[rf][1] += Sc[rf][s][3];
            }
        #pragma unroll
        for (int rf = 0; rf < 2; rf++)
            #pragma unroll
            for (int hh = 0; hh < 2; hh++) {
                sm[rf][hh] += __shfl_xor_sync(0xffffffffu, sm[rf][hh], 1);
                sm[rf][hh] += __shfl_xor_sync(0xffffffffu, sm[rf][hh], 2);
            }
        if ((lane & 3) == 0) {
            #pragma unroll
            for (int rf = 0; rf < 2; rf++) {
                psum[wq*64 + r0 + rf*16]     = sm[rf][0];
                psum[wq*64 + r0 + rf*16 + 8] = sm[rf][1];
            }
        }
        // write P (split) to smem for PV
        {
            uint32_t rx = (uint32_t)((lane >> 2) << 4);
            #pragma unroll
            for (int rf = 0; rf < 2; rf++) {
                int r = r0 + rf*16;
                #pragma unroll
                for (int s = 0; s < 2; s++) {
                    int j = wq*16 + s*8 + (lane & 3)*2;
                    uint32_t o0 = (uint32_t)r*128 + (((uint32_t)j*2) ^ rx);
                    uint32_t o1 = (uint32_t)(r+8)*128 + (((uint32_t)j*2) ^ rx);
                    __nv_bfloat16 h0,lo0,h1,lo1;
                    bsplit(Sc[rf][s][0],h0,lo0); bsplit(Sc[rf][s][1],h1,lo1);
                    *(__nv_bfloat162*)(smem + A_SP + o0)        = __halves2bfloat162(h0,h1);
                    *(__nv_bfloat162*)(smem + A_SP + 8192 + o0) = __halves2bfloat162(lo0,lo1);
                    bsplit(Sc[rf][s][2],h0,lo0); bsplit(Sc[rf][s][3],h1,lo1);
                    *(__nv_bfloat162*)(smem + A_SP + o1)        = __halves2bfloat162(h0,h1);
                    *(__nv_bfloat162*)(smem + A_SP + 8192 + o1) = __halves2bfloat162(lo0,lo1);
                }
            }
        }
        #pragma unroll
        for (int rf = 0; rf < 2; rf++)
            #pragma unroll
            for (int g = 0; g < 6; g++) {
                Oa[rf][g][0] *= al[rf][0]; Oa[rf][g][1] *= al[rf][0];
                Oa[rf][g][2] *= al[rf][1]; Oa[rf][g][3] *= al[rf][1];
            }
        __syncthreads();
        #pragma unroll
        for (int rf = 0; rf < 2; rf++)
            #pragma unroll
            for (int hh = 0; hh < 2; hh++) {
                int row = r0 + rf*16 + hh*8;
                lreg[rf][hh] = lreg[rf][hh]*al[rf][hh]
                             + psum[row] + psum[64 + row] + psum[128 + row] + psum[192 + row];
            }

        // --- PV: O += P . V : warp covers 32 rows x 48 d (d-slice wq) ---
        mbar_wait(bV, ph);
        #pragma unroll
        for (int kp = 0; kp < 4; kp++) {
            uint32_t ao = ((uint32_t)(kp*32) + akh) ^ axk;
            uint32_t phr[2][4], plr[2][4];
            #pragma unroll
            for (int rf = 0; rf < 2; rf++) {
                ldm4(phr[rf], sb + A_SP + aOff0 + rf*2048 + ao);
                ldm4(plr[rf], sb + A_SP + 8192 + aOff0 + rf*2048 + ao);
            }
            uint32_t vhh[3][4], vll[3][4];
            #pragma unroll
            for (int pr = 0; pr < 3; pr++) {
                uint32_t rowb = (uint32_t)(wq*48 + pr*16 + bRowLow);
                uint32_t bo = rowb*128 + (((uint32_t)(kp*32) + bkh) ^ axk);
                ldm4(vhh[pr], sb + A_SV + bo);
                ldm4(vll[pr], sb + A_SV + 24576 + bo);
            }
            #pragma unroll
            for (int rf = 0; rf < 2; rf++)
                #pragma unroll
                for (int pr = 0; pr < 3; pr++)
                    #pragma unroll
                    for (int s = 0; s < 2; s++)
                        mma_bf16(Oa[rf][pr*2+s], phr[rf], vhh[pr][s*2], vhh[pr][s*2+1]);
            #pragma unroll
            for (int rf = 0; rf < 2; rf++)
                #pragma unroll
                for (int pr = 0; pr < 3; pr++)
                    #pragma unroll
                    for (int s = 0; s < 2; s++)
                        mma_bf16(Oa[rf][pr*2+s], phr[rf], vll[pr][s*2], vll[pr][s*2+1]);
            #pragma unroll
            for (int rf = 0; rf < 2; rf++)
                #pragma unroll
                for (int pr = 0; pr < 3; pr++)
                    #pragma unroll
                    for (int s = 0; s < 2; s++)
                        mma_bf16(Oa[rf][pr*2+s], plr[rf], vhh[pr][s*2], vhh[pr][s*2+1]);
        }
        __syncthreads();   // V consumed
        if (tid == 0 && jt + 1 < 24) {
            mbar_expect_tx(bV, 49152);
            tma3d(sb + A_SV, &tmVt, bb*1536 + (jt+1)*64, h*192, 0, bV);
        }
    }

    // epilogue: O / l -> g_Os split planes
    #pragma unroll
    for (int rf = 0; rf < 2; rf++) {
        float inv0 = 1.f / lreg[rf][0], inv1 = 1.f / lreg[rf][1];
        int r = r0 + rf*16;
        #pragma unroll
        for (int g = 0; g < 6; g++) {
            int d = h*192 + wq*48 + g*8 + (lane & 3)*2;
            size_t o0 = (size_t)(bb*1536 + i0 + r)*1536 + d;
            size_t o1 = (size_t)(bb*1536 + i0 + r + 8)*1536 + d;
            __nv_bfloat16 h0,lo0,h1,lo1;
            bsplit(Oa[rf][g][0]*inv0,h0,lo0); bsplit(Oa[rf][g][1]*inv0,h1,lo1);
            *(__nv_bfloat162*)(g_Os + o0)            = __halves2bfloat162(h0,h1);
            *(__nv_bfloat162*)(g_Os + OS_PLANE + o0) = __halves2bfloat162(lo0,lo1);
            bsplit(Oa[rf][g][2]*inv1,h0,lo0); bsplit(Oa[rf][g][3]*inv1,h1,lo1);
            *(__nv_bfloat162*)(g_Os + o1)            = __halves2bfloat162(h0,h1);
            *(__nv_bfloat162*)(g_Os + OS_PLANE + o1) = __halves2bfloat162(lo0,lo1);
        }
    }
}

// ---------------- host ----------------
typedef CUresult (*PFN_encT)(CUtensorMap*, CUtensorMapDataType, cuuint32_t, void*,
                             const cuuint64_t*, const cuuint64_t*, const cuuint32_t*,
                             const cuuint32_t*, CUtensorMapInterleave, CUtensorMapSwizzle,
                             CUtensorMapL2promotion, CUtensorMapFloatOOBfill);

static void enc3(PFN_encT fn, CUtensorMap* m, void* p, unsigned long long k,
                 unsigned long long rows, unsigned box1) {
    cuuint64_t dims[3] = {k, rows, 2};
    cuuint64_t st[2]   = {k * 2, k * rows * 2};
    cuuint32_t box[3]  = {64, box1, 2};
    cuuint32_t es[3]   = {1, 1, 1};
    fn(m, CU_TENSOR_MAP_DATA_TYPE_BFLOAT16, 3, p, dims, st, box, es,
       CU_TENSOR_MAP_INTERLEAVE_NONE, CU_TENSOR_MAP_SWIZZLE_128B,
       CU_TENSOR_MAP_L2_PROMOTION_L2_128B, CU_TENSOR_MAP_FLOAT_OOB_FILL_NONE);
}

extern "C" void kernel_launch(void* const* d_in, const int* in_sizes, int n_in,
                              void* d_out, int out_size) {
    const float* x    = (const float*)d_in[0];
    const float* Wq   = (const float*)d_in[1];
    const float* Wk   = (const float*)d_in[2];
    const float* Wv   = (const float*)d_in[3];
    const float* Wrel = (const float*)d_in[4];
    const float* Wout = (const float*)d_in[5];
    const float* bo   = (const float*)d_in[6];
    const float* rcb  = (const float*)d_in[7];
    const float* rpb  = (const float*)d_in[8];

    cudaDriverEntryPointQueryResult qr;
    void* fp = nullptr;
    cudaGetDriverEntryPoint("cuTensorMapEncodeTiled", &fp, cudaEnableDefault, &qr);
    PFN_encT enc = (PFN_encT)fp;

    __nv_bfloat16 *xs, *ws, *wouts, *wrels, *poss, *Os, *Ks, *Vts, *relks;
    cudaGetSymbolAddress((void**)&xs,    g_xs);
    cudaGetSymbolAddress((void**)&ws,    g_ws);
    cudaGetSymbolAddress((void**)&wouts, g_wouts);
    cudaGetSymbolAddress((void**)&wrels, g_wrels);
    cudaGetSymbolAddress((void**)&poss,  g_poss);
    cudaGetSymbolAddress((void**)&Os,    g_Os);
    cudaGetSymbolAddress((void**)&Ks,    g_Ks);
    cudaGetSymbolAddress((void**)&Vts,   g_Vts);
    cudaGetSymbolAddress((void**)&relks, g_relks);

    CUtensorMap tA_x, tB_qkv, tA_pos, tB_rel, tA_o, tB_out, tmK, tmRel, tmVt;
    enc3(enc, &tA_x,   xs,    DIM, MROWS, 128);
    enc3(enc, &tB_qkv, ws,    DIM, NQKV,  256);
    enc3(enc, &tA_pos, poss,  FS,  MROWS, 128);
    enc3(enc, &tB_rel, wrels, FS,  HDK,   256);
    enc3(enc, &tA_o,   Os,    HDV, MROWS, 128);
    enc3(enc, &tB_out, wouts, HDV, DIM,   256);
    enc3(enc, &tmK,    Ks,    HDK, MROWS, 64);
    enc3(enc, &tmRel,  relks, HDK, MROWS, 128);
    enc3(enc, &tmVt,   Vts,   MROWS, HDV, 192);

    cudaFuncSetAttribute(gemm_mma<1>, cudaFuncAttributeMaxDynamicSharedMemorySize, GSMEM);
    cudaFuncSetAttribute(gemm_mma<2>, cudaFuncAttributeMaxDynamicSharedMemorySize, GSMEM);
    cudaFuncSetAttribute(attn_mma,    cudaFuncAttributeMaxDynamicSharedMemorySize, A_SMEM);

    split_x<<<(MROWS*DIM/4 + 255)/256, 256>>>(x);                                   // 0
    prep_kernel<<<PREP_BLOCKS, 256>>>(Wq, Wk, Wv, Wrel, Wout);                      // 1
    gemm_mma<1><<<dim3(12, 24), 256, GSMEM>>>(tA_x, tB_qkv, tA_pos, tB_rel, nullptr, nullptr, 24, 0);  // 2
    attn_mma<<<dim3(N_SEQ/64, NB*HEADS), 256, A_SMEM>>>(tmK, tmRel, tmVt, rcb, rpb); // 3 (abs 5 -> profiled)
    gemm_mma<2><<<dim3(6, 24), 256, GSMEM>>>(tA_o, tB_out, tA_o, tB_out, (float*)d_out, bo, 24, DIM);  // 4
}

// round 11
// speedup vs baseline: 1.0006x; 1.0006x over previous
#include <cuda_runtime.h>
#include <cuda.h>
#include <cuda_bf16.h>
#include <math.h>
#include <float.h>
#include <stdint.h>

#define N_SEQ 1536
#define NB    2
#define HEADS 8
#define DK    64
#define DV    192
#define DIM   1536
#define FS    192
#define HDK   (HEADS*DK)
#define HDV   (HEADS*DV)
#define MROWS (NB*N_SEQ)   // 3072
#define NQKV  2560

__device__ __align__(1024) __nv_bfloat16 g_xs   [2*MROWS*DIM];
__device__ __align__(1024) __nv_bfloat16 g_ws   [2*NQKV*DIM];
__device__ __align__(1024) __nv_bfloat16 g_wouts[2*DIM*HDV];
__device__ __align__(1024) __nv_bfloat16 g_wrels[2*HDK*FS];
__device__ __align__(1024) __nv_bfloat16 g_poss [2*MROWS*FS];
__device__ __align__(1024) __nv_bfloat16 g_Os   [2*MROWS*HDV];
__device__ __align__(1024) __nv_bfloat16 g_Ks   [2*MROWS*HDK];
__device__ __align__(1024) __nv_bfloat16 g_Vts  [2*HDV*MROWS];
__device__ __align__(1024) __nv_bfloat16 g_relks[2*MROWS*HDK];
__device__ __align__(1024) float g_Q   [MROWS*HDK];

#define XS_PLANE    ((size_t)MROWS*DIM)
#define WS_PLANE    ((size_t)NQKV*DIM)
#define WOUTS_PLANE ((size_t)DIM*HDV)
#define WRELS_PLANE ((size_t)HDK*FS)
#define POSS_PLANE  ((size_t)MROWS*FS)
#define OS_PLANE    ((size_t)MROWS*HDV)
#define KS_PLANE    ((size_t)MROWS*HDK)
#define VTS_PLANE   ((size_t)HDV*MROWS)
#define RELKS_PLANE ((size_t)MROWS*HDK)

__device__ __forceinline__ void bsplit(float v, __nv_bfloat16& h, __nv_bfloat16& l) {
    h = __float2bfloat16(v);
    l = __float2bfloat16(__fsub_rn(v, __bfloat162float(h)));
}
__device__ __forceinline__ uint32_t smem_u32(const void* p) {
    uint32_t a;
    asm("{ .reg .u64 t; cvta.to.shared.u64 t, %1; cvt.u32.u64 %0, t; }" : "=r"(a) : "l"(p));
    return a;
}
__device__ __forceinline__ void mbar_init(uint32_t a, uint32_t c) {
    asm volatile("mbarrier.init.shared.b64 [%0], %1;" :: "r"(a), "r"(c) : "memory");
}
__device__ __forceinline__ void mbar_expect_tx(uint32_t a, uint32_t b) {
    asm volatile("mbarrier.arrive.expect_tx.shared.b64 _, [%0], %1;" :: "r"(a), "r"(b) : "memory");
}
__device__ __forceinline__ void mbar_wait(uint32_t a, uint32_t ph) {
    asm volatile(
        "{\n\t.reg .pred P;\n\t"
        "W%=:\n\t"
        "mbarrier.try_wait.parity.acquire.cta.shared::cta.b64 P, [%0], %1, 0x989680;\n\t"
        "@P bra.uni D%=;\n\t"
        "bra.uni W%=;\n\t"
        "D%=:\n\t}"
        :: "r"(a), "r"(ph) : "memory");
}
__device__ __forceinline__ void tma3d(uint32_t dst, const CUtensorMap* tm, int x, int y, int z, uint32_t bar) {
    asm volatile(
        "cp.async.bulk.tensor.3d.shared::cta.global.tile.mbarrier::complete_tx::bytes "
        "[%0], [%1, {%2, %3, %4}], [%5];"
        :: "r"(dst), "l"(tm), "r"(x), "r"(y), "r"(z), "r"(bar) : "memory");
}
__device__ __forceinline__ void ldm4(uint32_t* r, uint32_t addr) {
    asm volatile("ldmatrix.sync.aligned.m8n8.x4.shared.b16 {%0,%1,%2,%3}, [%4];"
                 : "=r"(r[0]), "=r"(r[1]), "=r"(r[2]), "=r"(r[3]) : "r"(addr));
}
__device__ __forceinline__ void mma_bf16(float* c, const uint32_t* a, uint32_t b0, uint32_t b1) {
    asm volatile("mma.sync.aligned.m16n8k16.row.col.f32.bf16.bf16.f32 "
                 "{%0,%1,%2,%3}, {%4,%5,%6,%7}, {%8,%9}, {%0,%1,%2,%3};"
                 : "+f"(c[0]), "+f"(c[1]), "+f"(c[2]), "+f"(c[3])
                 : "r"(a[0]), "r"(a[1]), "r"(a[2]), "r"(a[3]), "r"(b0), "r"(b1));
}

// ---------------- split helpers ----------------
__device__ __forceinline__ void split_quad(const float* __restrict__ src,
                                           __nv_bfloat16* __restrict__ dh,
                                           __nv_bfloat16* __restrict__ dl, int i) {
    float4 v = ((const float4*)src)[i];
    __nv_bfloat16 h0,l0,h1,l1,h2,l2,h3,l3;
    bsplit(v.x,h0,l0); bsplit(v.y,h1,l1); bsplit(v.z,h2,l2); bsplit(v.w,h3,l3);
    ((__nv_bfloat162*)dh)[2*i]   = __halves2bfloat162(h0,h1);
    ((__nv_bfloat162*)dh)[2*i+1] = __halves2bfloat162(h2,h3);
    ((__nv_bfloat162*)dl)[2*i]   = __halves2bfloat162(l0,l1);
    ((__nv_bfloat162*)dl)[2*i+1] = __halves2bfloat162(l2,l3);
}

__global__ void split_x(const float* __restrict__ x) {
    int i = blockIdx.x * 256 + threadIdx.x;
    if (i < MROWS*DIM/4) split_quad(x, g_xs, g_xs + XS_PLANE, i);
}

// ---------------- fp32-exact transcendentals + XLA lgamma ----------------
__device__ __forceinline__ float logf_cr(float x)   { return (float)log((double)x); }
__device__ __forceinline__ float log1pf_cr(float x) { return (float)log1p((double)x); }
__device__ __forceinline__ float expf_cr(float x)   { return (float)exp((double)x); }

__device__ float lgamma_xla_f32(float input) {
    const float kCoef[8] = {
        676.520368121885098567009190444019f, -1259.13921672240287047156078755283f,
        771.3234287776530788486528258894f,   -176.61502916214059906584551354f,
        12.507343278686904814458936853f,     -0.13857109526572011689554707f,
        9.984369578019570859563e-6f,         1.50563273514931155834e-7f};
    float z = __fsub_rn(input, 1.f);
    float x = 0.99999999999980993227684700473478f;
    #pragma unroll
    for (int i = 0; i < 8; i++)
        x = __fadd_rn(x, __fdiv_rn(kCoef[i], __fadd_rn(__fadd_rn(z, (float)i), 1.f)));
    float t     = __fadd_rn(7.5f, z);
    float log_t = __fadd_rn(2.01490302054226772453f, log1pf_cr(__fdiv_rn(z, 7.5f)));
    float term  = __fmul_rn(__fsub_rn(__fadd_rn(z, 0.5f), __fdiv_rn(t, log_t)), log_t);
    return __fadd_rn(__fadd_rn(0.91893853320467274178f, term), logf_cr(x));
}

// ---------------- fused prep: pos-embed blocks + weight-split blocks ----------------
#define WQ_Q   (HDK*DIM/4)
#define WV_Q   (HDV*DIM/4)
#define WREL_Q (HDK*FS/4)
#define WOUT_Q (DIM*HDV/4)
#define WTOT_Q (WQ_Q*2 + WV_Q + WREL_Q + WOUT_Q)
#define PREP_BLOCKS (MROWS + (WTOT_Q + 255)/256)

__global__ void prep_kernel(const float* __restrict__ Wq, const float* __restrict__ Wk,
                            const float* __restrict__ Wv, const float* __restrict__ Wrel,
                            const float* __restrict__ Wout) {
    if (blockIdx.x >= MROWS) {
        int i = (blockIdx.x - MROWS) * 256 + threadIdx.x;
        if (i >= WTOT_Q) return;
        if (i < WQ_Q)   { split_quad(Wq,   g_ws,            g_ws + WS_PLANE,            i); return; }
        i -= WQ_Q;
        if (i < WQ_Q)   { split_quad(Wk,   g_ws + 512*DIM,  g_ws + WS_PLANE + 512*DIM,  i); return; }
        i -= WQ_Q;
        if (i < WV_Q)   { split_quad(Wv,   g_ws + 1024*DIM, g_ws + WS_PLANE + 1024*DIM, i); return; }
        i -= WV_Q;
        if (i < WREL_Q) { split_quad(Wrel, g_wrels,         g_wrels + WRELS_PLANE,      i); return; }
        i -= WREL_Q;
        split_quad(Wout, g_wouts, g_wouts + WOUTS_PLANE, i);
        return;
    }
    int p = blockIdx.x, t = threadIdx.x;
    size_t base = (size_t)p * FS;
    __shared__ float gprob[32];
    if (p == MROWS - 1) {
        if (t < 96) {
            g_poss[base + t] = __float2bfloat16(0.f);
            g_poss[base + t + POSS_PLANE] = __float2bfloat16(0.f);
            g_poss[base + 96 + t] = __float2bfloat16(0.f);
            g_poss[base + 96 + t + POSS_PLANE] = __float2bfloat16(0.f);
        }
        return;
    }
    const double LN2 = 0.6931471805599453;
    double adist = fabs((double)(p - (N_SEQ - 1)));
    float adist_f = (float)adist;
    float sgn = (p > N_SEQ-1) ? 1.f : ((p < N_SEQ-1) ? -1.f : 0.f);
    float val = 0.f;
    if (t < 32) {
        double max_range = log((double)N_SEQ) / LN2;
        double hl = exp2(3.0 + (double)t * (max_range - 3.0) / 31.0);
        val = (float)exp(-LN2 / hl * adist);
    } else if (t < 64) {
        double width = exp2((double)(t - 31)) - 1.0;
        val = (width > adist) ? 1.f : 0.f;
    } else if (t < 96) {
        int c = t - 64;
        float mean = 48.f * (float)(c + 1);
        float cc   = __fdiv_rn(mean, 24.f);
        float conc = __fmul_rn(cc, cc);
        float rate = __fdiv_rn(mean, 576.f);
        float log_unnorm = __fsub_rn(__fmul_rn(__fsub_rn(conc, 1.f), logf_cr(adist_f)),
                                     __fmul_rn(rate, adist_f));
        float log_norm   = __fsub_rn(lgamma_xla_f32(conc), __fmul_rn(conc, logf_cr(rate)));
        gprob[c] = __fadd_rn(expf_cr(__fsub_rn(log_unnorm, log_norm)), 1e-8f);
    }
    __syncthreads();
    if (t >= 64 && t < 96) {
        float mx = gprob[0];
        #pragma unroll
        for (int i = 1; i < 32; i++) mx = fmaxf(mx, gprob[i]);
        val = __fdiv_rn(gprob[t - 64], mx);
    }
    if (t < 96) {
        __nv_bfloat16 h, l;
        bsplit(val, h, l);
        g_poss[base + t] = h; g_poss[base + t + POSS_PLANE] = l;
        bsplit(sgn * val, h, l);
        g_poss[base + 96 + t] = h; g_poss[base + 96 + t + POSS_PLANE] = l;
    }
}

// ---------------- bf16x2 GEMM via mma.sync + TMA: C[M,N] = A·B^T ----------------
#define G_ABYTES 32768
#define G_BBYTES 65536
#define G_BUF    (G_ABYTES + G_BBYTES)
#define GSO_BF   0
#define GSO_TL   1024
#define GSMEM    (GSO_TL + 2*G_BUF)
#define VT_STRIDE 136

template<int MODE>
__global__ __launch_bounds__(256) void gemm_mma(
    const __grid_constant__ CUtensorMap tmA,
    const __grid_constant__ CUtensorMap tmB,
    const __grid_constant__ CUtensorMap tmA2,
    const __grid_constant__ CUtensorMap tmB2,
    float* __restrict__ C0, const float* __restrict__ bias, int nchunks, int ldc)
{
    extern __shared__ __align__(1024) char smem[];
    const uint32_t sb = smem_u32(smem);
    const int tid = threadIdx.x, wid = tid >> 5, lane = tid & 31;
    const int m0 = blockIdx.y * 128;
    const bool isRel = (MODE == 1) && (blockIdx.x >= 10);
    const CUtensorMap* pA = isRel ? &tmA2 : &tmA;
    const CUtensorMap* pB = isRel ? &tmB2 : &tmB;
    const int n0 = isRel ? (blockIdx.x - 10) * 256 : blockIdx.x * 256;
    const int nch = isRel ? 3 : nchunks;
    const int wr = wid >> 2, wc = wid & 3;

    if (tid == 0) {
        mbar_init(sb + GSO_BF, 1);
        mbar_init(sb + GSO_BF + 8, 1);
        asm volatile("fence.proxy.async.shared::cta;" ::: "memory");
    }
    __syncthreads();
    if (tid == 0) {
        #pragma unroll
        for (int c = 0; c < 2; c++) {
            uint32_t buf = sb + GSO_TL + c * G_BUF, bar = sb + GSO_BF + 8 * c;
            mbar_expect_tx(bar, G_BUF);
            tma3d(buf,            pA, c * 64, m0, 0, bar);
            tma3d(buf + G_ABYTES, pB, c * 64, n0, 0, bar);
        }
    }

    const uint32_t aBase = (uint32_t)(wr*64 + (lane & 15)) * 128;
    const uint32_t axk   = (uint32_t)((lane & 7) << 4);
    const uint32_t akh   = (uint32_t)((lane >> 4) * 16);
    const int bRowLow    = (lane & 7) + ((lane >> 4) & 1) * 8;
    const uint32_t bkh   = (uint32_t)(((lane >> 3) & 1) * 16);

    float acc[4][8][4];
    #pragma unroll
    for (int f = 0; f < 4; f++)
        #pragma unroll
        for (int g = 0; g < 8; g++)
            #pragma unroll
            for (int q = 0; q < 4; q++) acc[f][g][q] = 0.f;

    for (int c = 0; c < nch; c++) {
        mbar_wait(sb + GSO_BF + 8 * (c & 1), (uint32_t)((c >> 1) & 1));
        const uint32_t bufb = sb + GSO_TL + (c & 1) * G_BUF;
        #pragma unroll
        for (int ks = 0; ks < 4; ks++) {
            const uint32_t kb = (uint32_t)(ks * 32);
            const uint32_t aoff = (kb + akh) ^ axk;
            uint32_t Ah[4][4], Al[4][4];
            #pragma unroll
            for (int f = 0; f < 4; f++) ldm4(Ah[f], bufb + aBase + f * 2048 + aoff);
            #pragma unroll
            for (int f = 0; f < 4; f++) ldm4(Al[f], bufb + 16384 + aBase + f * 2048 + aoff);
            #pragma unroll
            for (int gg = 0; gg < 4; gg++) {
                uint32_t brow = (uint32_t)(wc*64 + gg*16 + bRowLow);
                uint32_t bo = brow * 128 + ((kb + bkh) ^ axk);
                uint32_t Bh[4], Bl[4];
                ldm4(Bh, bufb + 32768 + bo);
                ldm4(Bl, bufb + 65536 + bo);
                #pragma unroll
                for (int f = 0; f < 4; f++) {
                    mma_bf16(acc[f][gg*2+0], Ah[f], Bh[0], Bh[1]);
                    mma_bf16(acc[f][gg*2+1], Ah[f], Bh[2], Bh[3]);
                }
                #pragma unroll
                for (int f = 0; f < 4; f++) {
                    mma_bf16(acc[f][gg*2+0], Ah[f], Bl[0], Bl[1]);
                    mma_bf16(acc[f][gg*2+1], Ah[f], Bl[2], Bl[3]);
                }
                #pragma unroll
                for (int f = 0; f < 4; f++) {
                    mma_bf16(acc[f][gg*2+0], Al[f], Bh[0], Bh[1]);
                    mma_bf16(acc[f][gg*2+1], Al[f], Bh[2], Bh[3]);
                }
            }
        }
        __syncthreads();
        if (tid == 0 && c + 2 < nch) {
            uint32_t buf = sb + GSO_TL + (c & 1) * G_BUF, bar = sb + GSO_BF + 8 * (c & 1);
            mbar_expect_tx(bar, G_BUF);
            tma3d(buf,            pA, (c + 2) * 64, m0, 0, bar);
            tma3d(buf + G_ABYTES, pB, (c + 2) * 64, n0, 0, bar);
        }
    }

    // ---------------- epilogue ----------------
    if (MODE == 1 && !isRel && n0 >= 1024) {
        __nv_bfloat16* sTh = (__nv_bfloat16*)(smem + GSO_TL);
        __nv_bfloat16* sTl = sTh + 256 * VT_STRIDE;
        #pragma unroll
        for (int f = 0; f < 4; f++) {
            int mloc = wr*64 + f*16 + (lane >> 2);
            #pragma unroll
            for (int gg = 0; gg < 4; gg++)
                #pragma unroll
                for (int s = 0; s < 2; s++) {
                    int cn = wc*64 + gg*16 + s*8 + (lane & 3)*2;
                    const float* a = acc[f][gg*2+s];
                    __nv_bfloat16 h0,l0,h1,l1,h2,l2,h3,l3;
                    bsplit(a[0],h0,l0); bsplit(a[1],h1,l1);
                    bsplit(a[2],h2,l2); bsplit(a[3],h3,l3);
                    sTh[cn*VT_STRIDE + mloc]         = h0;
                    sTh[(cn+1)*VT_STRIDE + mloc]     = h1;
                    sTh[cn*VT_STRIDE + mloc + 8]     = h2;
                    sTh[(cn+1)*VT_STRIDE + mloc + 8] = h3;
                    sTl[cn*VT_STRIDE + mloc]         = l0;
                    sTl[(cn+1)*VT_STRIDE + mloc]     = l1;
                    sTl[cn*VT_STRIDE + mloc + 8]     = l2;
                    sTl[(cn+1)*VT_STRIDE + mloc + 8] = l3;
                }
        }
        __syncthreads();
        int r = tid;
        size_t gbase = (size_t)(n0 - 1024 + r) * 3072 + m0;
        const uint4* sph = (const uint4*)(sTh + r * VT_STRIDE);
        const uint4* spl = (const uint4*)(sTl + r * VT_STRIDE);
        uint4* dph = (uint4*)(g_Vts + gbase);
        uint4* dpl = (uint4*)(g_Vts + VTS_PLANE + gbase);
        #pragma unroll
        for (int q = 0; q < 16; q++) dph[q] = sph[q];
        #pragma unroll
        for (int q = 0; q < 16; q++) dpl[q] = spl[q];
        return;
    }
    #pragma unroll
    for (int f = 0; f < 4; f++) {
        int m = m0 + wr*64 + f*16 + (lane >> 2);
        #pragma unroll
        for (int gg = 0; gg < 4; gg++)
            #pragma unroll
            for (int s = 0; s < 2; s++) {
                int cn = wc*64 + gg*16 + s*8 + (lane & 3)*2;
                float v0 = acc[f][gg*2+s][0], v1 = acc[f][gg*2+s][1];
                float v2 = acc[f][gg*2+s][2], v3 = acc[f][gg*2+s][3];
                if (MODE == 2) {
                    float2 bv = *(const float2*)(bias + n0 + cn);
                    v0 += bv.x; v1 += bv.y; v2 += bv.x; v3 += bv.y;
                    *(float2*)(C0 + (size_t)m * ldc + n0 + cn)       = make_float2(v0, v1);
                    *(float2*)(C0 + (size_t)(m + 8) * ldc + n0 + cn) = make_float2(v2, v3);
                } else if (isRel) {
                    __nv_bfloat16 h0,l0,h1,l1;
                    bsplit(v0,h0,l0); bsplit(v1,h1,l1);
                    *(__nv_bfloat162*)(g_relks + (size_t)m*512 + n0 + cn) = __halves2bfloat162(h0,h1);
                    *(__nv_bfloat162*)(g_relks + RELKS_PLANE + (size_t)m*512 + n0 + cn) = __halves2bfloat162(l0,l1);
                    bsplit(v2,h0,l0); bsplit(v3,h1,l1);
                    *(__nv_bfloat162*)(g_relks + (size_t)(m+8)*512 + n0 + cn) = __halves2bfloat162(h0,h1);
                    *(__nv_bfloat162*)(g_relks + RELKS_PLANE + (size_t)(m+8)*512 + n0 + cn) = __halves2bfloat162(l0,l1);
                } else if (n0 < 512) {
                    *(float2*)(g_Q + (size_t)m * 512 + n0 + cn)       = make_float2(v0, v1);
                    *(float2*)(g_Q + (size_t)(m + 8) * 512 + n0 + cn) = make_float2(v2, v3);
                } else {
                    int kc = n0 - 512 + cn;
                    __nv_bfloat16 h0,l0,h1,l1;
                    bsplit(v0,h0,l0); bsplit(v1,h1,l1);
                    *(__nv_bfloat162*)(g_Ks + (size_t)m*512 + kc) = __halves2bfloat162(h0,h1);
                    *(__nv_bfloat162*)(g_Ks + KS_PLANE + (size_t)m*512 + kc) = __halves2bfloat162(l0,l1);
                    bsplit(v2,h0,l0); bsplit(v3,h1,l1);
                    *(__nv_bfloat162*)(g_Ks + (size_t)(m+8)*512 + kc) = __halves2bfloat162(h0,h1);
                    *(__nv_bfloat162*)(g_Ks + KS_PLANE + (size_t)(m+8)*512 + kc) = __halves2bfloat162(l0,l1);
                }
            }
    }
}

// ---------------- tensor-core flash attention with relative shift ----------------
// 8 warps = (wq = wid&3: N-slice) x (rh = wid>>2: 32-row half).
// R: warp 32 rows x 32 p; S: 32 rows x 16 j; PV: 32 rows x 48 d.
#define A_SQ    0          // qch 0, qcl 8192, qrh 16384, qrl 24576
#define A_SK    32768
#define A_SREL  49152
#define A_SV    81920
#define A_SP    131072
#define A_SR    147456     // fp32 64 x 132
#define A_SPM   181248     // pmax [4][64]
#define A_SPS   182272     // psum [4][64]
#define A_SBAR  183296
#define A_SMEM  183312

__global__ __launch_bounds__(256) void attn_mma(
    const __grid_constant__ CUtensorMap tmK,
    const __grid_constant__ CUtensorMap tmRel,
    const __grid_constant__ CUtensorMap tmVt,
    const float* __restrict__ rcb, const float* __restrict__ rpb)
{
    extern __shared__ __align__(1024) char smem[];
    const uint32_t sb = smem_u32(smem);
    const int tid = threadIdx.x, wid = tid >> 5, lane = tid & 31;
    const int wq = wid & 3, rh = wid >> 2;
    const int bh = blockIdx.y, bb = bh >> 3, h = bh & 7;
    const int i0 = blockIdx.x * 64;

    float* Rsm  = (float*)(smem + A_SR);
    float* pmax = (float*)(smem + A_SPM);
    float* psum = (float*)(smem + A_SPS);
    const uint32_t bKR = sb + A_SBAR, bV = sb + A_SBAR + 8;

    if (tid == 0) {
        mbar_init(bKR, 1); mbar_init(bV, 1);
        asm volatile("fence.proxy.async.shared::cta;" ::: "memory");
    }
    __syncthreads();
    if (tid == 0) {
        mbar_expect_tx(bKR, 49152);
        tma3d(sb + A_SK,   &tmK,   h*64, bb*1536, 0, bKR);
        tma3d(sb + A_SREL, &tmRel, h*64, 1472 - i0, 0, bKR);
        mbar_expect_tx(bV, 49152);
        tma3d(sb + A_SV,   &tmVt,  bb*1536, h*192, 0, bV);
    }
    // build Q tiles
    {
        int row = tid >> 2;
        int c0 = (tid & 3) * 16;
        const float* qrow = g_Q + (size_t)(bb*1536 + i0 + row)*512 + h*64 + c0;
        const float* cb = rcb + h*64 + c0;
        const float* pb = rpb + h*64 + c0;
        uint32_t rx = (uint32_t)((row & 7) << 4);
        #pragma unroll
        for (int c = 0; c < 16; c += 2) {
            float q0 = qrow[c]*0.125f, q1 = qrow[c+1]*0.125f;
            float a0 = q0 + cb[c], a1 = q1 + cb[c+1];
            float b0 = q0 + pb[c], b1 = q1 + pb[c+1];
            uint32_t off = (uint32_t)row*128 + (((uint32_t)(c0 + c)*2) ^ rx);
            __nv_bfloat16 h0,l0,h1,l1;
            bsplit(a0,h0,l0); bsplit(a1,h1,l1);
            *(__nv_bfloat162*)(smem + A_SQ + off)        = __halves2bfloat162(h0,h1);
            *(__nv_bfloat162*)(smem + A_SQ + 8192 + off) = __halves2bfloat162(l0,l1);
            bsplit(b0,h0,l0); bsplit(b1,h1,l1);
            *(__nv_bfloat162*)(smem + A_SQ + 16384 + off) = __halves2bfloat162(h0,h1);
            *(__nv_bfloat162*)(smem + A_SQ + 24576 + off) = __halves2bfloat162(l0,l1);
        }
    }
    __syncthreads();

    const uint32_t aOff0 = (uint32_t)(rh*32 + (lane & 15)) * 128;   // A frag rf=0; rf=1 -> +2048
    const uint32_t axk   = (uint32_t)((lane & 7) << 4);
    const uint32_t akh   = (uint32_t)((lane >> 4) * 16);
    const int bRowLow    = (lane & 7) + ((lane >> 4) & 1) * 8;
    const uint32_t bkh   = (uint32_t)(((lane >> 3) & 1) * 16);
    const int r0 = rh*32 + (lane >> 2);   // rows: r0+rf*16 (+8)

    float Oa[2][6][4];
    #pragma unroll
    for (int rf = 0; rf < 2; rf++)
        #pragma unroll
        for (int g = 0; g < 6; g++)
            #pragma unroll
            for (int q = 0; q < 4; q++) Oa[rf][g][q] = 0.f;
    float mreg[2][2] = {{-1e30f,-1e30f},{-1e30f,-1e30f}};
    float lreg[2][2] = {{0.f,0.f},{0.f,0.f}};

    #pragma unroll 1
    for (int jt = 0; jt < 24; jt++) {
        uint32_t ph = (uint32_t)(jt & 1);
        mbar_wait(bKR, ph);

        // --- R = Qr . relk^T : warp covers 32 rows x 32 p (p-slice wq) ---
        float Rc[2][4][4];
        #pragma unroll
        for (int rf = 0; rf < 2; rf++)
            #pragma unroll
            for (int g = 0; g < 4; g++)
                #pragma unroll
                for (int q = 0; q < 4; q++) Rc[rf][g][q] = 0.f;
        #pragma unroll
        for (int ks = 0; ks < 4; ks++) {
            uint32_t ao = ((uint32_t)(ks*32) + akh) ^ axk;
            uint32_t qh[2][4], ql[2][4];
            #pragma unroll
            for (int rf = 0; rf < 2; rf++) {
                ldm4(qh[rf], sb + A_SQ + 16384 + aOff0 + rf*2048 + ao);
                ldm4(ql[rf], sb + A_SQ + 24576 + aOff0 + rf*2048 + ao);
            }
            uint32_t bhh[2][4], bll[2][4];
            #pragma unroll
            for (int bf = 0; bf < 2; bf++) {
                uint32_t rowb = (uint32_t)(wq*32 + bf*16 + bRowLow);
                uint32_t bo = rowb*128 + (((uint32_t)(ks*32) + bkh) ^ axk);
                ldm4(bhh[bf], sb + A_SREL + bo);
                ldm4(bll[bf], sb + A_SREL + 16384 + bo);
            }
            #pragma unroll
            for (int rf = 0; rf < 2; rf++)
                #pragma unroll
                for (int bf = 0; bf < 2; bf++)
                    #pragma unroll
                    for (int s = 0; s < 2; s++)
                        mma_bf16(Rc[rf][bf*2+s], qh[rf], bhh[bf][s*2], bhh[bf][s*2+1]);
            #pragma unroll
            for (int rf = 0; rf < 2; rf++)
                #pragma unroll
                for (int bf = 0; bf < 2; bf++)
                    #pragma unroll
                    for (int s = 0; s < 2; s++)
                        mma_bf16(Rc[rf][bf*2+s], qh[rf], bll[bf][s*2], bll[bf][s*2+1]);
            #pragma unroll
            for (int rf = 0; rf < 2; rf++)
                #pragma unroll
                for (int bf = 0; bf < 2; bf++)
                    #pragma unroll
                    for (int s = 0; s < 2; s++)
                        mma_bf16(Rc[rf][bf*2+s], ql[rf], bhh[bf][s*2], bhh[bf][s*2+1]);
        }
        #pragma unroll
        for (int rf = 0; rf < 2; rf++) {
            int r = r0 + rf*16;
            #pragma unroll
            for (int g = 0; g < 4; g++) {
                int p = wq*32 + g*8 + (lane & 3)*2;
                *(float2*)(Rsm + r*132 + p)     = make_float2(Rc[rf][g][0], Rc[rf][g][1]);
                *(float2*)(Rsm + (r+8)*132 + p) = make_float2(Rc[rf][g][2], Rc[rf][g][3]);
            }
        }

        // --- content S = Qc . K^T : warp covers 32 rows x 16 j (j-slice wq) ---
        float Sc[2][2][4];
        #pragma unroll
        for (int rf = 0; rf < 2; rf++)
            #pragma unroll
            for (int s = 0; s < 2; s++)
                #pragma unroll
                for (int q = 0; q < 4; q++) Sc[rf][s][q] = 0.f;
        #pragma unroll
        for (int ks = 0; ks < 4; ks++) {
            uint32_t ao = ((uint32_t)(ks*32) + akh) ^ axk;
            uint32_t qh[2][4], ql[2][4];
            #pragma unroll
            for (int rf = 0; rf < 2; rf++) {
                ldm4(qh[rf], sb + A_SQ + aOff0 + rf*2048 + ao);
                ldm4(ql[rf], sb + A_SQ + 8192 + aOff0 + rf*2048 + ao);
            }
            uint32_t kh[4], kl[4];
            {
                uint32_t rowb = (uint32_t)(wq*16 + bRowLow);
                uint32_t bo = rowb*128 + (((uint32_t)(ks*32) + bkh) ^ axk);
                ldm4(kh, sb + A_SK + bo);
                ldm4(kl, sb + A_SK + 8192 + bo);
            }
            #pragma unroll
            for (int rf = 0; rf < 2; rf++)
                #pragma unroll
                for (int s = 0; s < 2; s++)
                    mma_bf16(Sc[rf][s], qh[rf], kh[s*2], kh[s*2+1]);
            #pragma unroll
            for (int rf = 0; rf < 2; rf++)
                #pragma unroll
                for (int s = 0; s < 2; s++)
                    mma_bf16(Sc[rf][s], qh[rf], kl[s*2], kl[s*2+1]);
            #pragma unroll
            for (int rf = 0; rf < 2; rf++)
                #pragma unroll
                for (int s = 0; s < 2; s++)
                    mma_bf16(Sc[rf][s], ql[rf], kh[s*2], kh[s*2+1]);
        }
        __syncthreads();   // R complete everywhere; K/rel smem consumed
        if (tid == 0 && jt + 1 < 24) {
            mbar_expect_tx(bKR, 49152);
            tma3d(sb + A_SK,   &tmK,   h*64, bb*1536 + (jt+1)*64, 0, bKR);
            tma3d(sb + A_SREL, &tmRel, h*64, (jt+1)*64 - i0 + 1472, 0, bKR);
        }

        // --- gather rel logits: S[i,j] += R[i, j-i+63] ---
        #pragma unroll
        for (int rf = 0; rf < 2; rf++) {
            int r = r0 + rf*16;
            #pragma unroll
            for (int s = 0; s < 2; s++) {
                int j = wq*16 + s*8 + (lane & 3)*2;
                Sc[rf][s][0] += Rsm[r*132 + (j - r + 63)];
                Sc[rf][s][1] += Rsm[r*132 + (j - r + 64)];
                Sc[rf][s][2] += Rsm[(r+8)*132 + (j - (r+8) + 63)];
                Sc[rf][s][3] += Rsm[(r+8)*132 + (j - (r+8) + 64)];
            }
        }

        // --- online softmax (cross-slice via smem partials [4][64]) ---
        float mx[2][2];
        #pragma unroll
        for (int rf = 0; rf < 2; rf++) {
            mx[rf][0] = fmaxf(fmaxf(Sc[rf][0][0], Sc[rf][0][1]), fmaxf(Sc[rf][1][0], Sc[rf][1][1]));
            mx[rf][1] = fmaxf(fmaxf(Sc[rf][0][2], Sc[rf][0][3]), fmaxf(Sc[rf][1][2], Sc[rf][1][3]));
        }
        #pragma unroll
        for (int rf = 0; rf < 2; rf++)
            #pragma unroll
            for (int hh = 0; hh < 2; hh++) {
                mx[rf][hh] = fmaxf(mx[rf][hh], __shfl_xor_sync(0xffffffffu, mx[rf][hh], 1));
                mx[rf][hh] = fmaxf(mx[rf][hh], __shfl_xor_sync(0xffffffffu, mx[rf][hh], 2));
            }
        if ((lane & 3) == 0) {
            #pragma unroll
            for (int rf = 0; rf < 2; rf++) {
                pmax[wq*64 + r0 + rf*16]     = mx[rf][0];
                pmax[wq*64 + r0 + rf*16 + 8] = mx[rf][1];
            }
        }
        __syncthreads();
        float mn[2][2], al[2][2];
        #pragma unroll
        for (int rf = 0; rf < 2; rf++)
            #pragma unroll
            for (int hh = 0; hh < 2; hh++) {
                int row = r0 + rf*16 + hh*8;
                float mval = fmaxf(fmaxf(pmax[row], pmax[64 + row]),
                                   fmaxf(pmax[128 + row], pmax[192 + row]));
                mn[rf][hh] = fmaxf(mreg[rf][hh], mval);
                al[rf][hh] = __expf(mreg[rf][hh] - mn[rf][hh]);
                mreg[rf][hh] = mn[rf][hh];
            }
        float sm[2][2] = {{0.f,0.f},{0.f,0.f}};
        #pragma unroll
        for (int rf = 0; rf < 2; rf++)
            #pragma unroll
            for (int s = 0; s < 2; s++) {
                Sc[rf][s][0] = __expf(Sc[rf][s][0] - mn[rf][0]); sm[rf][0] += Sc[rf][s][0];
                Sc[rf][s][1] = __expf(Sc[rf][s][1] - mn[rf][0]); sm[rf][0] += Sc[rf][s][1];
                Sc[rf][s][2] = __expf(Sc[rf][s][2] - mn[rf][1]); sm[rf][1] += Sc[rf][s][2];
                Sc[rf][s][3] = __expf(Sc[rf][s][3] - mn[rf][1]); sm[rf][1] += Sc[rf][s][3];
            }
        #pragma unroll
        for (int rf = 0; rf < 2; rf++)
            #pragma unroll
            for (int hh = 0; hh < 2; hh++) {
                sm[rf][hh] += __shfl_xor_sync(0xffffffffu, sm[rf][hh], 1);
                sm[rf][hh] += __shfl_xor_sync(0xffffffffu, sm[rf][hh], 2);
            }
        if ((lane & 3) == 0) {
            #pragma unroll
            for (int rf = 0; rf < 2; rf++) {
                psum[wq*64 + r0 + rf*16]     = sm[rf][0];
                psum[wq*64 + r0 + rf*16 + 8] = sm[rf][1];
            }
        }
        // write P (split) to smem for PV
        {
            uint32_t rx = (uint32_t)((lane >> 2) << 4);
            #pragma unroll
            for (int rf = 0; rf < 2; rf++) {
                int r = r0 + rf*16;
                #pragma unroll
                for (int s = 0; s < 2; s++) {
                    int j = wq*16 + s*8 + (lane & 3)*2;
                    uint32_t o0 = (uint32_t)r*128 + (((uint32_t)j*2) ^ rx);
                    uint32_t o1 = (uint32_t)(r+8)*128 + (((uint32_t)j*2) ^ rx);
                    __nv_bfloat16 h0,lo0,h1,lo1;
                    bsplit(Sc[rf][s][0],h0,lo0); bsplit(Sc[rf][s][1],h1,lo1);
                    *(__nv_bfloat162*)(smem + A_SP + o0)        = __halves2bfloat162(h0,h1);
                    *(__nv_bfloat162*)(smem + A_SP + 8192 + o0) = __halves2bfloat162(lo0,lo1);
                    bsplit(Sc[rf][s][2],h0,lo0); bsplit(Sc[rf][s][3],h1,lo1);
                    *(__nv_bfloat162*)(smem + A_SP + o1)        = __halves2bfloat162(h0,h1);
                    *(__nv_bfloat162*)(smem + A_SP + 8192 + o1) = __halves2bfloat162(lo0,lo1);
                }
            }
        }
        #pragma unroll
        for (int rf = 0; rf < 2; rf++)
            #pragma unroll
            for (int g = 0; g < 6; g++) {
                Oa[rf][g][0] *= al[rf][0]; Oa[rf][g][1] *= al[rf][0];
                Oa[rf][g][2] *= al[rf][1]; Oa[rf][g][3] *= al[rf][1];
            }
        __syncthreads();
        #pragma unroll
        for (int rf = 0; rf < 2; rf++)
            #pragma unroll
            for (int hh = 0; hh < 2; hh++) {
                int row = r0 + rf*16 + hh*8;
                lreg[rf][hh] = lreg[rf][hh]*al[rf][hh]
                             + psum[row] + psum[64 + row] + psum[128 + row] + psum[192 + row];
            }

        // --- PV: O += P . V : warp covers 32 rows x 48 d (d-slice wq) ---
        mbar_wait(bV, ph);
        #pragma unroll
        for (int kp = 0; kp < 4; kp++) {
            uint32_t ao = ((uint32_t)(kp*32) + akh) ^ axk;
            uint32_t phr[2][4], plr[2][4];
            #pragma unroll
            for (int rf = 0; rf < 2; rf++) {
                ldm4(phr[rf], sb + A_SP + aOff0 + rf*2048 + ao);
                ldm4(plr[rf], sb + A_SP + 8192 + aOff0 + rf*2048 + ao);
            }
            uint32_t vhh[3][4], vll[3][4];
            #pragma unroll
            for (int pr = 0; pr < 3; pr++) {
                uint32_t rowb = (uint32_t)(wq*48 + pr*16 + bRowLow);
                uint32_t bo = rowb*128 + (((uint32_t)(kp*32) + bkh) ^ axk);
                ldm4(vhh[pr], sb + A_SV + bo);
                ldm4(vll[pr], sb + A_SV + 24576 + bo);
            }
            #pragma unroll
            for (int rf = 0; rf < 2; rf++)
                #pragma unroll
                for (int pr = 0; pr < 3; pr++)
                    #pragma unroll
                    for (int s = 0; s < 2; s++)
                        mma_bf16(Oa[rf][pr*2+s], phr[rf], vhh[pr][s*2], vhh[pr][s*2+1]);
            #pragma unroll
            for (int rf = 0; rf < 2; rf++)
                #pragma unroll
                for (int pr = 0; pr < 3; pr++)
                    #pragma unroll
                    for (int s = 0; s < 2; s++)
                        mma_bf16(Oa[rf][pr*2+s], phr[rf], vll[pr][s*2], vll[pr][s*2+1]);
            #pragma unroll
            for (int rf = 0; rf < 2; rf++)
                #pragma unroll
                for (int pr = 0; pr < 3; pr++)
                    #pragma unroll
                    for (int s = 0; s < 2; s++)
                        mma_bf16(Oa[rf][pr*2+s], plr[rf], vhh[pr][s*2], vhh[pr][s*2+1]);
        }
        __syncthreads();   // V consumed
        if (tid == 0 && jt + 1 < 24) {
            mbar_expect_tx(bV, 49152);
            tma3d(sb + A_SV, &tmVt, bb*1536 + (jt+1)*64, h*192, 0, bV);
        }
    }

    // epilogue: O / l -> g_Os split planes
    #pragma unroll
    for (int rf = 0; rf < 2; rf++) {
        float inv0 = 1.f / lreg[rf][0], inv1 = 1.f / lreg[rf][1];
        int r = r0 + rf*16;
        #pragma unroll
        for (int g = 0; g < 6; g++) {
            int d = h*192 + wq*48 + g*8 + (lane & 3)*2;
            size_t o0 = (size_t)(bb*1536 + i0 + r)*1536 + d;
            size_t o1 = (size_t)(bb*1536 + i0 + r + 8)*1536 + d;
            __nv_bfloat16 h0,lo0,h1,lo1;
            bsplit(Oa[rf][g][0]*inv0,h0,lo0); bsplit(Oa[rf][g][1]*inv0,h1,lo1);
            *(__nv_bfloat162*)(g_Os + o0)            = __halves2bfloat162(h0,h1);
            *(__nv_bfloat162*)(g_Os + OS_PLANE + o0) = __halves2bfloat162(lo0,lo1);
            bsplit(Oa[rf][g][2]*inv1,h0,lo0); bsplit(Oa[rf][g][3]*inv1,h1,lo1);
            *(__nv_bfloat162*)(g_Os + o1)            = __halves2bfloat162(h0,h1);
            *(__nv_bfloat162*)(g_Os + OS_PLANE + o1) = __halves2bfloat162(lo0,lo1);
        }
    }
}

// ---------------- host ----------------
typedef CUresult (*PFN_encT)(CUtensorMap*, CUtensorMapDataType, cuuint32_t, void*,
                             const cuuint64_t*, const cuuint64_t*, const cuuint32_t*,
                             const cuuint32_t*, CUtensorMapInterleave, CUtensorMapSwizzle,
                             CUtensorMapL2promotion, CUtensorMapFloatOOBfill);

static void enc3(PFN_encT fn, CUtensorMap* m, void* p, unsigned long long k,
                 unsigned long long rows, unsigned box1) {
    cuuint64_t dims[3] = {k, rows, 2};
    cuuint64_t st[2]   = {k * 2, k * rows * 2};
    cuuint32_t box[3]  = {64, box1, 2};
    cuuint32_t es[3]   = {1, 1, 1};
    fn(m, CU_TENSOR_MAP_DATA_TYPE_BFLOAT16, 3, p, dims, st, box, es,
       CU_TENSOR_MAP_INTERLEAVE_NONE, CU_TENSOR_MAP_SWIZZLE_128B,
       CU_TENSOR_MAP_L2_PROMOTION_L2_128B, CU_TENSOR_MAP_FLOAT_OOB_FILL_NONE);
}

extern "C" void kernel_launch(void* const* d_in, const int* in_sizes, int n_in,
                              void* d_out, int out_size) {
    const float* x    = (const float*)d_in[0];
    const float* Wq   = (const float*)d_in[1];
    const float* Wk   = (const float*)d_in[2];
    const float* Wv   = (const float*)d_in[3];
    const float* Wrel = (const float*)d_in[4];
    const float* Wout = (const float*)d_in[5];
    const float* bo   = (const float*)d_in[6];
    const float* rcb  = (const float*)d_in[7];
    const float* rpb  = (const float*)d_in[8];

    cudaDriverEntryPointQueryResult qr;
    void* fp = nullptr;
    cudaGetDriverEntryPoint("cuTensorMapEncodeTiled", &fp, cudaEnableDefault, &qr);
    PFN_encT enc = (PFN_encT)fp;

    __nv_bfloat16 *xs, *ws, *wouts, *wrels, *poss, *Os, *Ks, *Vts, *relks;
    cudaGetSymbolAddress((void**)&xs,    g_xs);
    cudaGetSymbolAddress((void**)&ws,    g_ws);
    cudaGetSymbolAddress((void**)&wouts, g_wouts);
    cudaGetSymbolAddress((void**)&wrels, g_wrels);
    cudaGetSymbolAddress((void**)&poss,  g_poss);
    cudaGetSymbolAddress((void**)&Os,    g_Os);
    cudaGetSymbolAddress((void**)&Ks,    g_Ks);
    cudaGetSymbolAddress((void**)&Vts,   g_Vts);
    cudaGetSymbolAddress((void**)&relks, g_relks);

    CUtensorMap tA_x, tB_qkv, tA_pos, tB_rel, tA_o, tB_out, tmK, tmRel, tmVt;
    enc3(enc, &tA_x,   xs,    DIM, MROWS, 128);
    enc3(enc, &tB_qkv, ws,    DIM, NQKV,  256);
    enc3(enc, &tA_pos, poss,  FS,  MROWS, 128);
    enc3(enc, &tB_rel, wrels, FS,  HDK,   256);
    enc3(enc, &tA_o,   Os,    HDV, MROWS, 128);
    enc3(enc, &tB_out, wouts, HDV, DIM,   256);
    enc3(enc, &tmK,    Ks,    HDK, MROWS, 64);
    enc3(enc, &tmRel,  relks, HDK, MROWS, 128);
    enc3(enc, &tmVt,   Vts,   MROWS, HDV, 192);

    cudaFuncSetAttribute(gemm_mma<1>, cudaFuncAttributeMaxDynamicSharedMemorySize, GSMEM);
    cudaFuncSetAttribute(gemm_mma<2>, cudaFuncAttributeMaxDynamicSharedMemorySize, GSMEM);
    cudaFuncSetAttribute(attn_mma,    cudaFuncAttributeMaxDynamicSharedMemorySize, A_SMEM);

    split_x<<<(MROWS*DIM/4 + 255)/256, 256>>>(x);                                   // 0
    prep_kernel<<<PREP_BLOCKS, 256>>>(Wq, Wk, Wv, Wrel, Wout);                      // 1
    gemm_mma<1><<<dim3(12, 24), 256, GSMEM>>>(tA_x, tB_qkv, tA_pos, tB_rel, nullptr, nullptr, 24, 0);  // 2
    attn_mma<<<dim3(N_SEQ/64, NB*HEADS), 256, A_SMEM>>>(tmK, tmRel, tmVt, rcb, rpb); // 3 (abs 5 -> profiled)
    gemm_mma<2><<<dim3(6, 24), 256, GSMEM>>>(tA_o, tB_out, tA_o, tB_out, (float*)d_out, bo, 24, DIM);  // 4
}